// round 1
// baseline (speedup 1.0000x reference)
#include <cuda_runtime.h>
#include <cuda_bf16.h>
#include <cstdint>

// Problem constants (GCNEncoder_55052890800619)
#define NN 100000
#define DD 128
#define HH 256
#define EE 1600000

// ---------------- scratch (device globals; no allocations allowed) ----------
__device__ int   g_is64;
__device__ int   g_src[EE];
__device__ int   g_dst[EE];
__device__ int   g_cnt[NN];
__device__ int   g_rowptr[NN];
__device__ int   g_cursor[NN];
__device__ float g_dinv[NN];
__device__ int   g_bsums[128];
__device__ int   g_boffs[128];
__device__ int   g_csr_src[EE];
__device__ float g_csr_w[EE];
__device__ float g_xw1[(size_t)NN * HH];   // 102.4 MB
__device__ float g_x  [(size_t)NN * HH];   // 102.4 MB
__device__ float g_xw2[(size_t)NN * DD];   // 51.2 MB

// ---------------- small prep kernels ----------------------------------------
__global__ void zero_cnt_kernel(int n) {
    int i = blockIdx.x * blockDim.x + threadIdx.x;
    if (i < n) g_cnt[i] = 0;
}

// Detect whether edge_index is int64 (odd 32-bit words == 0 for non-negative
// values) or int32 (odd words are random node indices).
__global__ void detect_kernel(const unsigned int* __restrict__ p) {
    if (blockIdx.x == 0 && threadIdx.x == 0) {
        int any = 0;
        #pragma unroll 1
        for (int i = 0; i < 64; i++) {
            long long j = (long long)i * 24999 + 7;   // j in [0, 1.6M)
            any |= (p[2 * j + 1] != 0u);
        }
        g_is64 = any ? 0 : 1;
    }
}

__global__ void convert_count_kernel(const void* __restrict__ eptr, int E) {
    int e = blockIdx.x * blockDim.x + threadIdx.x;
    if (e >= E) return;
    int s, d;
    if (g_is64) {
        const long long* q = (const long long*)eptr;
        s = (int)q[e];
        d = (int)q[(size_t)E + e];
    } else {
        const int* q = (const int*)eptr;
        s = q[e];
        d = q[(size_t)E + e];
    }
    g_src[e] = s;
    g_dst[e] = d;
    atomicAdd(&g_cnt[d], 1);
}

__global__ void dinv_kernel(int n) {
    int i = blockIdx.x * blockDim.x + threadIdx.x;
    if (i < n) g_dinv[i] = rsqrtf((float)g_cnt[i] + 1.0f);
}

// Exclusive scan of g_cnt into g_rowptr (per 1024-block), block totals to g_bsums.
__global__ void scan_block_kernel(int n) {
    __shared__ int sh[1024];
    int gid = blockIdx.x * 1024 + threadIdx.x;
    int v = (gid < n) ? g_cnt[gid] : 0;
    sh[threadIdx.x] = v;
    __syncthreads();
    for (int off = 1; off < 1024; off <<= 1) {
        int t = (threadIdx.x >= (unsigned)off) ? sh[threadIdx.x - off] : 0;
        __syncthreads();
        sh[threadIdx.x] += t;
        __syncthreads();
    }
    if (gid < n) g_rowptr[gid] = sh[threadIdx.x] - v;   // exclusive
    if (threadIdx.x == 1023) g_bsums[blockIdx.x] = sh[1023];
}

__global__ void scan_sums_kernel(int nb) {
    __shared__ int sh[128];
    int v = (threadIdx.x < (unsigned)nb) ? g_bsums[threadIdx.x] : 0;
    sh[threadIdx.x] = v;
    __syncthreads();
    for (int off = 1; off < 128; off <<= 1) {
        int t = (threadIdx.x >= (unsigned)off) ? sh[threadIdx.x - off] : 0;
        __syncthreads();
        sh[threadIdx.x] += t;
        __syncthreads();
    }
    if (threadIdx.x < (unsigned)nb) g_boffs[threadIdx.x] = sh[threadIdx.x] - v;
}

__global__ void add_offsets_kernel(int n) {
    int i = blockIdx.x * blockDim.x + threadIdx.x;
    if (i >= n) return;
    int r = g_rowptr[i] + g_boffs[i >> 10];
    g_rowptr[i] = r;
    g_cursor[i] = r;
}

__global__ void csr_fill_kernel(int E) {
    int e = blockIdx.x * blockDim.x + threadIdx.x;
    if (e >= E) return;
    int s = g_src[e];
    int d = g_dst[e];
    int pos = atomicAdd(&g_cursor[d], 1);
    g_csr_src[pos] = s;
    g_csr_w[pos]   = g_dinv[s] * g_dinv[d];
}

// ---------------- SGEMM: C[M,Nc] = A[M,K] @ B[K,Nc] --------------------------
// BM=128, BN=128, BK=16, 256 threads, 8x8 per thread.
__global__ void __launch_bounds__(256)
sgemm_kernel(const float* __restrict__ A, const float* __restrict__ B,
             float* __restrict__ C, int M, int Nc, int K)
{
    const int BM = 128, BN = 128, BK = 16, TM = 8, TN = 8;
    __shared__ float As[BK][BM];
    __shared__ float Bs[BK][BN + 4];

    int tid  = threadIdx.x;
    int brow = blockIdx.y * BM;
    int bcol = blockIdx.x * BN;
    int tm   = (tid / 16) * TM;
    int tn   = (tid % 16) * TN;

    float acc[TM][TN];
    #pragma unroll
    for (int i = 0; i < TM; i++)
        #pragma unroll
        for (int j = 0; j < TN; j++) acc[i][j] = 0.0f;

    for (int k0 = 0; k0 < K; k0 += BK) {
        // A tile: BMxBK = 512 float4, 2 per thread
        #pragma unroll
        for (int t = 0; t < 2; t++) {
            int i  = tid * 2 + t;
            int r  = i >> 2;          // / (BK/4)
            int kq = i & 3;
            int grow = brow + r;
            float4 v = make_float4(0.f, 0.f, 0.f, 0.f);
            if (grow < M)
                v = *(const float4*)(A + (size_t)grow * K + k0 + kq * 4);
            As[kq * 4 + 0][r] = v.x;
            As[kq * 4 + 1][r] = v.y;
            As[kq * 4 + 2][r] = v.z;
            As[kq * 4 + 3][r] = v.w;
        }
        // B tile: BKxBN = 512 float4, 2 per thread (Nc divisible by 128)
        #pragma unroll
        for (int t = 0; t < 2; t++) {
            int i  = tid * 2 + t;
            int r  = i >> 5;          // / (BN/4)
            int cq = i & 31;
            float4 v = *(const float4*)(B + (size_t)(k0 + r) * Nc + bcol + cq * 4);
            *(float4*)&Bs[r][cq * 4] = v;
        }
        __syncthreads();

        #pragma unroll
        for (int kk = 0; kk < BK; kk++) {
            float a[TM], b[TN];
            #pragma unroll
            for (int i = 0; i < TM; i++) a[i] = As[kk][tm + i];
            #pragma unroll
            for (int j = 0; j < TN; j++) b[j] = Bs[kk][tn + j];
            #pragma unroll
            for (int i = 0; i < TM; i++)
                #pragma unroll
                for (int j = 0; j < TN; j++)
                    acc[i][j] = fmaf(a[i], b[j], acc[i][j]);
        }
        __syncthreads();
    }

    #pragma unroll
    for (int i = 0; i < TM; i++) {
        int grow = brow + tm + i;
        if (grow >= M) continue;
        #pragma unroll
        for (int j = 0; j < TN; j += 4) {
            float4 v = make_float4(acc[i][j], acc[i][j + 1],
                                   acc[i][j + 2], acc[i][j + 3]);
            *(float4*)(C + (size_t)grow * Nc + bcol + tn + j) = v;
        }
    }
}

// ---------------- aggregation: warp per node --------------------------------
// out[i] = (maybe relu)( sum_{j in nbrs(i)} w_j * xw[src_j] + dinv_i^2 * xw[i] + bias )
template <int VEC, bool RELU>
__global__ void __launch_bounds__(256)
agg_kernel(const float* __restrict__ xw, const float* __restrict__ bias,
           float* __restrict__ out, int n)
{
    int warp = (blockIdx.x * 256 + threadIdx.x) >> 5;
    int lane = threadIdx.x & 31;
    if (warp >= n) return;

    const int COLSV = VEC * 32;   // float4 per row
    float4 acc[VEC];

    float dsq = g_dinv[warp];
    dsq *= dsq;
    const float4* selfp = (const float4*)xw + (size_t)warp * COLSV;
    #pragma unroll
    for (int v = 0; v < VEC; v++) {
        float4 t = selfp[lane * VEC + v];
        acc[v] = make_float4(t.x * dsq, t.y * dsq, t.z * dsq, t.w * dsq);
    }

    int r0 = g_rowptr[warp];
    int c  = g_cnt[warp];
    for (int j = r0; j < r0 + c; j++) {
        int   s = g_csr_src[j];
        float w = g_csr_w[j];
        const float4* p = (const float4*)xw + (size_t)s * COLSV;
        #pragma unroll
        for (int v = 0; v < VEC; v++) {
            float4 t = p[lane * VEC + v];
            acc[v].x = fmaf(t.x, w, acc[v].x);
            acc[v].y = fmaf(t.y, w, acc[v].y);
            acc[v].z = fmaf(t.z, w, acc[v].z);
            acc[v].w = fmaf(t.w, w, acc[v].w);
        }
    }

    const float4* bp = (const float4*)bias;
    float4* op = (float4*)out + (size_t)warp * COLSV;
    #pragma unroll
    for (int v = 0; v < VEC; v++) {
        float4 b = bp[lane * VEC + v];
        float4 r = make_float4(acc[v].x + b.x, acc[v].y + b.y,
                               acc[v].z + b.z, acc[v].w + b.w);
        if (RELU) {
            r.x = fmaxf(r.x, 0.f);
            r.y = fmaxf(r.y, 0.f);
            r.z = fmaxf(r.z, 0.f);
            r.w = fmaxf(r.w, 0.f);
        }
        op[lane * VEC + v] = r;
    }
}

// ---------------- launch -----------------------------------------------------
extern "C" void kernel_launch(void* const* d_in, const int* in_sizes, int n_in,
                              void* d_out, int out_size)
{
    const float* emb = (const float*)d_in[0];   // [N, D]
    const float* W1  = (const float*)d_in[1];   // [D, H]
    const float* b1  = (const float*)d_in[2];   // [H]
    const float* W2  = (const float*)d_in[3];   // [H, D]
    const float* b2  = (const float*)d_in[4];   // [D]
    const void*  eix = d_in[5];                 // [2, E] int64 or int32
    float* out = (float*)d_out;                 // [N, D]

    const int D = in_sizes[4];          // 128
    const int H = in_sizes[2];          // 256
    const int N = in_sizes[0] / D;      // 100000
    const int E = in_sizes[5] / 2;      // 1600000
    const int NB = (N + 1023) / 1024;   // scan blocks (98)

    // device-global scratch pointers
    float *p_xw1, *p_x, *p_xw2;
    cudaGetSymbolAddress((void**)&p_xw1, g_xw1);
    cudaGetSymbolAddress((void**)&p_x,   g_x);
    cudaGetSymbolAddress((void**)&p_xw2, g_xw2);

    // ---- graph prep: counts, dinv, CSR ----
    zero_cnt_kernel<<<(N + 255) / 256, 256>>>(N);
    detect_kernel<<<1, 32>>>((const unsigned int*)eix);
    convert_count_kernel<<<(E + 255) / 256, 256>>>(eix, E);
    dinv_kernel<<<(N + 255) / 256, 256>>>(N);
    scan_block_kernel<<<NB, 1024>>>(N);
    scan_sums_kernel<<<1, 128>>>(NB);
    add_offsets_kernel<<<(N + 255) / 256, 256>>>(N);
    csr_fill_kernel<<<(E + 255) / 256, 256>>>(E);

    // ---- layer 1: xw1 = emb @ W1 ; x = relu(agg(xw1) + b1) ----
    {
        dim3 grid((H + 127) / 128, (N + 127) / 128);
        sgemm_kernel<<<grid, 256>>>(emb, W1, p_xw1, N, H, D);
    }
    agg_kernel<2, true><<<(N + 7) / 8, 256>>>(p_xw1, b1, p_x, N);

    // ---- layer 2: xw2 = x @ W2 ; out = agg(xw2) + b2 ----
    {
        dim3 grid((D + 127) / 128, (N + 127) / 128);
        sgemm_kernel<<<grid, 256>>>(p_x, W2, p_xw2, N, D, H);
    }
    agg_kernel<1, false><<<(N + 7) / 8, 256>>>(p_xw2, b2, out, N);
}

// round 2
// speedup vs baseline: 1.3621x; 1.3621x over previous
#include <cuda_runtime.h>
#include <cuda_bf16.h>
#include <cstdint>

// Problem constants (GCNEncoder_55052890800619)
#define NN 100000
#define DD 128
#define HH 256
#define EE 1600000

// ---------------- scratch (device globals; no allocations allowed) ----------
__device__ int   g_is64;
__device__ int   g_src[EE];
__device__ int   g_dst[EE];
__device__ int   g_cnt[NN];
__device__ int   g_rowptr[NN];
__device__ int   g_cursor[NN];
__device__ float g_dinv[NN];
__device__ int   g_bsums[128];
__device__ int   g_boffs[128];
__device__ int   g_csr_src[EE];
__device__ float g_csr_w[EE];
__device__ float g_aggemb[(size_t)NN * DD];  // 51.2 MB  agg(emb)
__device__ float g_x     [(size_t)NN * HH];  // 102.4 MB relu(agg(emb)@W1+b1)
__device__ float g_xw2   [(size_t)NN * DD];  // 51.2 MB  x@W2

// ---------------- small prep kernels ----------------------------------------
__global__ void zero_cnt_kernel(int n) {
    int i = blockIdx.x * blockDim.x + threadIdx.x;
    if (i < n) g_cnt[i] = 0;
}

// Detect whether edge_index is int64 (odd 32-bit words == 0 for non-negative
// values) or int32.
__global__ void detect_kernel(const unsigned int* __restrict__ p) {
    if (blockIdx.x == 0 && threadIdx.x == 0) {
        int any = 0;
        #pragma unroll 1
        for (int i = 0; i < 64; i++) {
            long long j = (long long)i * 24999 + 7;   // j in [0, 1.6M)
            any |= (p[2 * j + 1] != 0u);
        }
        g_is64 = any ? 0 : 1;
    }
}

__global__ void convert_count_kernel(const void* __restrict__ eptr, int E) {
    int e = blockIdx.x * blockDim.x + threadIdx.x;
    if (e >= E) return;
    int s, d;
    if (g_is64) {
        const long long* q = (const long long*)eptr;
        s = (int)q[e];
        d = (int)q[(size_t)E + e];
    } else {
        const int* q = (const int*)eptr;
        s = q[e];
        d = q[(size_t)E + e];
    }
    g_src[e] = s;
    g_dst[e] = d;
    atomicAdd(&g_cnt[d], 1);
}

__global__ void dinv_kernel(int n) {
    int i = blockIdx.x * blockDim.x + threadIdx.x;
    if (i < n) g_dinv[i] = rsqrtf((float)g_cnt[i] + 1.0f);
}

__global__ void scan_block_kernel(int n) {
    __shared__ int sh[1024];
    int gid = blockIdx.x * 1024 + threadIdx.x;
    int v = (gid < n) ? g_cnt[gid] : 0;
    sh[threadIdx.x] = v;
    __syncthreads();
    for (int off = 1; off < 1024; off <<= 1) {
        int t = (threadIdx.x >= (unsigned)off) ? sh[threadIdx.x - off] : 0;
        __syncthreads();
        sh[threadIdx.x] += t;
        __syncthreads();
    }
    if (gid < n) g_rowptr[gid] = sh[threadIdx.x] - v;   // exclusive
    if (threadIdx.x == 1023) g_bsums[blockIdx.x] = sh[1023];
}

__global__ void scan_sums_kernel(int nb) {
    __shared__ int sh[128];
    int v = (threadIdx.x < (unsigned)nb) ? g_bsums[threadIdx.x] : 0;
    sh[threadIdx.x] = v;
    __syncthreads();
    for (int off = 1; off < 128; off <<= 1) {
        int t = (threadIdx.x >= (unsigned)off) ? sh[threadIdx.x - off] : 0;
        __syncthreads();
        sh[threadIdx.x] += t;
        __syncthreads();
    }
    if (threadIdx.x < (unsigned)nb) g_boffs[threadIdx.x] = sh[threadIdx.x] - v;
}

__global__ void add_offsets_kernel(int n) {
    int i = blockIdx.x * blockDim.x + threadIdx.x;
    if (i >= n) return;
    int r = g_rowptr[i] + g_boffs[i >> 10];
    g_rowptr[i] = r;
    g_cursor[i] = r;
}

__global__ void csr_fill_kernel(int E) {
    int e = blockIdx.x * blockDim.x + threadIdx.x;
    if (e >= E) return;
    int s = g_src[e];
    int d = g_dst[e];
    int pos = atomicAdd(&g_cursor[d], 1);
    g_csr_src[pos] = s;
    g_csr_w[pos]   = g_dinv[s] * g_dinv[d];
}

// ---------------- tf32 helpers ----------------------------------------------
__device__ __forceinline__ void split_tf32(float x, uint32_t& hi, uint32_t& lo) {
    uint32_t h;
    asm("cvt.rna.tf32.f32 %0, %1;" : "=r"(h) : "f"(x));
    float r = x - __uint_as_float(h);
    asm("cvt.rna.tf32.f32 %0, %1;" : "=r"(lo) : "f"(r));
    hi = h;
}

__device__ __forceinline__ void mma8(float* c, const uint32_t* a, const uint32_t* b) {
    asm volatile(
        "mma.sync.aligned.m16n8k8.row.col.f32.tf32.tf32.f32 "
        "{%0,%1,%2,%3}, {%4,%5,%6,%7}, {%8,%9}, {%0,%1,%2,%3};"
        : "+f"(c[0]), "+f"(c[1]), "+f"(c[2]), "+f"(c[3])
        : "r"(a[0]), "r"(a[1]), "r"(a[2]), "r"(a[3]), "r"(b[0]), "r"(b[1]));
}

// ---------------- GEMM: C[M,N] = A[M,K] @ B[K,N] via 3xTF32 tensor cores -----
// BM=128, BN=128, BK=32, 256 threads = 8 warps, warp tile 32x64.
#define GBM 128
#define GBN 128
#define GBK 32

template <bool RELU_BIAS>
__global__ void __launch_bounds__(256)
gemm_tf32(const float* __restrict__ A, const float* __restrict__ B,
          const float* __restrict__ bias, float* __restrict__ C,
          int M, int N, int K)
{
    __shared__ float As[GBK][GBM + 4];
    __shared__ float Bs[GBK][GBN + 4];

    const int tid  = threadIdx.x;
    const int wid  = tid >> 5;
    const int lane = tid & 31;
    const int g    = lane >> 2;   // group id (0..7)
    const int t    = lane & 3;    // thread in group (0..3)
    const int brow = blockIdx.y * GBM;
    const int bcol = blockIdx.x * GBN;
    const int wm   = (wid >> 1) * 32;   // warp row offset: 0,32,64,96
    const int wn   = (wid & 1) * 64;    // warp col offset: 0,64

    float acc[2][8][4];
    #pragma unroll
    for (int mt = 0; mt < 2; mt++)
        #pragma unroll
        for (int nt = 0; nt < 8; nt++)
            #pragma unroll
            for (int i = 0; i < 4; i++) acc[mt][nt][i] = 0.0f;

    for (int k0 = 0; k0 < K; k0 += GBK) {
        // A tile 128x32: 1024 float4, 4 per thread (transpose to K-major)
        #pragma unroll
        for (int q = 0; q < 4; q++) {
            int id  = tid + q * 256;
            int row = id >> 3;        // 0..127
            int kq  = id & 7;         // float4 index along K
            float4 v = make_float4(0.f, 0.f, 0.f, 0.f);
            if (brow + row < M)
                v = *(const float4*)(A + (size_t)(brow + row) * K + k0 + kq * 4);
            As[kq * 4 + 0][row] = v.x;
            As[kq * 4 + 1][row] = v.y;
            As[kq * 4 + 2][row] = v.z;
            As[kq * 4 + 3][row] = v.w;
        }
        // B tile 32x128: 1024 float4, 4 per thread (keep row-major)
        #pragma unroll
        for (int q = 0; q < 4; q++) {
            int id  = tid + q * 256;
            int row = id >> 5;        // k in 0..31
            int nq  = id & 31;        // float4 index along N
            float4 v = *(const float4*)(B + (size_t)(k0 + row) * N + bcol + nq * 4);
            *(float4*)&Bs[row][nq * 4] = v;
        }
        __syncthreads();

        #pragma unroll
        for (int ks = 0; ks < 4; ks++) {
            const int kb = ks * 8;
            // A fragments for 2 m-tiles, hi/lo split
            uint32_t ahi[2][4], alo[2][4];
            #pragma unroll
            for (int mt = 0; mt < 2; mt++) {
                int m0 = wm + mt * 16;
                split_tf32(As[kb + t    ][m0 + g    ], ahi[mt][0], alo[mt][0]);
                split_tf32(As[kb + t    ][m0 + g + 8], ahi[mt][1], alo[mt][1]);
                split_tf32(As[kb + t + 4][m0 + g    ], ahi[mt][2], alo[mt][2]);
                split_tf32(As[kb + t + 4][m0 + g + 8], ahi[mt][3], alo[mt][3]);
            }
            #pragma unroll
            for (int nt = 0; nt < 8; nt++) {
                int n0 = wn + nt * 8;
                uint32_t bhi[2], blo[2];
                split_tf32(Bs[kb + t    ][n0 + g], bhi[0], blo[0]);
                split_tf32(Bs[kb + t + 4][n0 + g], bhi[1], blo[1]);
                #pragma unroll
                for (int mt = 0; mt < 2; mt++) {
                    mma8(acc[mt][nt], ahi[mt], bhi);
                    mma8(acc[mt][nt], ahi[mt], blo);
                    mma8(acc[mt][nt], alo[mt], bhi);
                }
            }
        }
        __syncthreads();
    }

    // epilogue: optional bias + relu, float2 stores
    #pragma unroll
    for (int nt = 0; nt < 8; nt++) {
        int col = bcol + wn + nt * 8 + 2 * t;
        float b0 = 0.f, b1 = 0.f;
        if (RELU_BIAS) { b0 = bias[col]; b1 = bias[col + 1]; }
        #pragma unroll
        for (int mt = 0; mt < 2; mt++) {
            int r0 = brow + wm + mt * 16 + g;
            float2 v0 = make_float2(acc[mt][nt][0] + b0, acc[mt][nt][1] + b1);
            float2 v1 = make_float2(acc[mt][nt][2] + b0, acc[mt][nt][3] + b1);
            if (RELU_BIAS) {
                v0.x = fmaxf(v0.x, 0.f); v0.y = fmaxf(v0.y, 0.f);
                v1.x = fmaxf(v1.x, 0.f); v1.y = fmaxf(v1.y, 0.f);
            }
            if (r0 < M)     *(float2*)(C + (size_t)r0 * N + col) = v0;
            if (r0 + 8 < M) *(float2*)(C + (size_t)(r0 + 8) * N + col) = v1;
        }
    }
}

// ---------------- aggregation (128 cols): warp per node ----------------------
// out[i] = sum_{j in nbrs(i)} w_j * xw[src_j] + dinv_i^2 * xw[i] (+ bias)
template <bool ADD_BIAS>
__global__ void __launch_bounds__(256)
agg128(const float* __restrict__ xw, const float* __restrict__ bias,
       float* __restrict__ out, int n)
{
    int node = (blockIdx.x * 256 + threadIdx.x) >> 5;
    int lane = threadIdx.x & 31;
    if (node >= n) return;

    float dsq = g_dinv[node];
    dsq *= dsq;
    float4 tv = *((const float4*)xw + (size_t)node * 32 + lane);
    float4 acc = make_float4(tv.x * dsq, tv.y * dsq, tv.z * dsq, tv.w * dsq);

    int r0 = g_rowptr[node];
    int c  = g_cnt[node];
    for (int j = r0; j < r0 + c; j++) {
        int   s = g_csr_src[j];
        float w = g_csr_w[j];
        float4 p = *((const float4*)xw + (size_t)s * 32 + lane);
        acc.x = fmaf(p.x, w, acc.x);
        acc.y = fmaf(p.y, w, acc.y);
        acc.z = fmaf(p.z, w, acc.z);
        acc.w = fmaf(p.w, w, acc.w);
    }

    if (ADD_BIAS) {
        float4 b = *((const float4*)bias + lane);
        acc.x += b.x; acc.y += b.y; acc.z += b.z; acc.w += b.w;
    }
    *((float4*)out + (size_t)node * 32 + lane) = acc;
}

// ---------------- launch -----------------------------------------------------
extern "C" void kernel_launch(void* const* d_in, const int* in_sizes, int n_in,
                              void* d_out, int out_size)
{
    const float* emb = (const float*)d_in[0];   // [N, D]
    const float* W1  = (const float*)d_in[1];   // [D, H]
    const float* b1  = (const float*)d_in[2];   // [H]
    const float* W2  = (const float*)d_in[3];   // [H, D]
    const float* b2  = (const float*)d_in[4];   // [D]
    const void*  eix = d_in[5];                 // [2, E] int64 or int32
    float* out = (float*)d_out;                 // [N, D]

    const int D = in_sizes[4];          // 128
    const int H = in_sizes[2];          // 256
    const int N = in_sizes[0] / D;      // 100000
    const int E = in_sizes[5] / 2;      // 1600000
    const int NB = (N + 1023) / 1024;   // scan blocks (98)

    float *p_aggemb, *p_x, *p_xw2;
    cudaGetSymbolAddress((void**)&p_aggemb, g_aggemb);
    cudaGetSymbolAddress((void**)&p_x,      g_x);
    cudaGetSymbolAddress((void**)&p_xw2,    g_xw2);

    // ---- graph prep: counts, dinv, CSR ----
    zero_cnt_kernel<<<(N + 255) / 256, 256>>>(N);
    detect_kernel<<<1, 32>>>((const unsigned int*)eix);
    convert_count_kernel<<<(E + 255) / 256, 256>>>(eix, E);
    dinv_kernel<<<(N + 255) / 256, 256>>>(N);
    scan_block_kernel<<<NB, 1024>>>(N);
    scan_sums_kernel<<<1, 128>>>(NB);
    add_offsets_kernel<<<(N + 255) / 256, 256>>>(N);
    csr_fill_kernel<<<(E + 255) / 256, 256>>>(E);

    // ---- layer 1: aggemb = agg(emb); x = relu(aggemb @ W1 + b1) ----
    // (agg is linear: agg(emb @ W1) == agg(emb) @ W1 — aggregate on 128 dims)
    agg128<false><<<(N + 7) / 8, 256>>>(emb, nullptr, p_aggemb, N);
    {
        dim3 grid(H / GBN, (N + GBM - 1) / GBM);
        gemm_tf32<true><<<grid, 256>>>(p_aggemb, W1, b1, p_x, N, H, D);
    }

    // ---- layer 2: xw2 = x @ W2; out = agg(xw2) + b2 ----
    {
        dim3 grid(D / GBN, (N + GBM - 1) / GBM);
        gemm_tf32<false><<<grid, 256>>>(p_x, W2, nullptr, p_xw2, N, D, H);
    }
    agg128<true><<<(N + 7) / 8, 256>>>(p_xw2, b2, out, N);
}

// round 3
// speedup vs baseline: 1.3753x; 1.0096x over previous
#include <cuda_runtime.h>
#include <cuda_bf16.h>
#include <cstdint>

// Problem constants (GCNEncoder_55052890800619)
#define NN 100000
#define DD 128
#define HH 256
#define EE 1600000

// ---------------- scratch (device globals; no allocations allowed) ----------
__device__ int   g_is64;
__device__ int   g_src[EE];
__device__ int   g_dst[EE];
__device__ int   g_cnt[NN];
__device__ int   g_rowptr[NN];
__device__ int   g_cursor[NN];
__device__ float g_dinv[NN];
__device__ int   g_bsums[128];
__device__ float g_aggemb[(size_t)NN * DD];  // 51.2 MB  agg(emb)
__device__ float g_x     [(size_t)NN * HH];  // 102.4 MB relu(agg(emb)@W1+b1)
__device__ float g_xw2   [(size_t)NN * DD];  // 51.2 MB  x@W2
__device__ int   g_csr_src[EE];
__device__ float g_csr_w[EE];

// ---------------- prep kernels (fused to 5 launches) -------------------------
// 1) zero counts + dtype detect
__global__ void zero_detect_kernel(const unsigned int* __restrict__ p, int n) {
    int i = blockIdx.x * blockDim.x + threadIdx.x;
    if (i < n) g_cnt[i] = 0;
    if (blockIdx.x == 0 && threadIdx.x == 0) {
        int any = 0;
        #pragma unroll 1
        for (int k = 0; k < 64; k++) {
            long long j = (long long)k * 24999 + 7;   // j in [0, 1.6M)
            any |= (p[2 * j + 1] != 0u);
        }
        g_is64 = any ? 0 : 1;
    }
}

// 2) convert edges to int32 + degree count
__global__ void convert_count_kernel(const void* __restrict__ eptr, int E) {
    int e = blockIdx.x * blockDim.x + threadIdx.x;
    if (e >= E) return;
    int s, d;
    if (g_is64) {
        const long long* q = (const long long*)eptr;
        s = (int)q[e];
        d = (int)q[(size_t)E + e];
    } else {
        const int* q = (const int*)eptr;
        s = q[e];
        d = q[(size_t)E + e];
    }
    g_src[e] = s;
    g_dst[e] = d;
    atomicAdd(&g_cnt[d], 1);
}

// 3) per-1024-block exclusive scan of counts + dinv
__global__ void scanblock_dinv_kernel(int n) {
    __shared__ int sh[1024];
    int gid = blockIdx.x * 1024 + threadIdx.x;
    int v = (gid < n) ? g_cnt[gid] : 0;
    if (gid < n) g_dinv[gid] = rsqrtf((float)v + 1.0f);
    sh[threadIdx.x] = v;
    __syncthreads();
    for (int off = 1; off < 1024; off <<= 1) {
        int t = (threadIdx.x >= (unsigned)off) ? sh[threadIdx.x - off] : 0;
        __syncthreads();
        sh[threadIdx.x] += t;
        __syncthreads();
    }
    if (gid < n) g_rowptr[gid] = sh[threadIdx.x] - v;   // exclusive within block
    if (threadIdx.x == 1023) g_bsums[blockIdx.x] = sh[1023];
}

// 4) add block offsets (each block redundantly scans the <=128 block sums)
__global__ void add_offsets_kernel(int n, int nb) {
    __shared__ int sh[128];
    int tid = threadIdx.x;
    if (tid < 128) sh[tid] = (tid < nb) ? g_bsums[tid] : 0;
    __syncthreads();
    for (int off = 1; off < 128; off <<= 1) {
        int t = (tid >= (unsigned)off && tid < 128) ? sh[tid - off] : 0;
        __syncthreads();
        if (tid < 128) sh[tid] += t;
        __syncthreads();
    }
    int i = blockIdx.x * 256 + tid;
    if (i >= n) return;
    int j = i >> 10;
    int off = (j == 0) ? 0 : sh[j - 1];
    int r = g_rowptr[i] + off;
    g_rowptr[i] = r;
    g_cursor[i] = r;
}

// 5) scatter edges into CSR
__global__ void csr_fill_kernel(int E) {
    int e = blockIdx.x * blockDim.x + threadIdx.x;
    if (e >= E) return;
    int s = g_src[e];
    int d = g_dst[e];
    int pos = atomicAdd(&g_cursor[d], 1);
    g_csr_src[pos] = s;
    g_csr_w[pos]   = g_dinv[s] * g_dinv[d];
}

// ---------------- bf16 split helpers ----------------------------------------
// pack two consecutive-k values (x0 lower half, x1 upper half), hi + residual
__device__ __forceinline__ void split_pack(float x0, float x1,
                                           uint32_t& hi, uint32_t& lo) {
    uint32_t h;
    asm("cvt.rn.bf16x2.f32 %0, %1, %2;" : "=r"(h) : "f"(x1), "f"(x0));
    float e0 = x0 - __uint_as_float(h << 16);
    float e1 = x1 - __uint_as_float(h & 0xffff0000u);
    asm("cvt.rn.bf16x2.f32 %0, %1, %2;" : "=r"(lo) : "f"(e1), "f"(e0));
    hi = h;
}

__device__ __forceinline__ void mma16(float* c, const uint32_t* a, const uint32_t* b) {
    asm volatile(
        "mma.sync.aligned.m16n8k16.row.col.f32.bf16.bf16.f32 "
        "{%0,%1,%2,%3}, {%4,%5,%6,%7}, {%8,%9}, {%0,%1,%2,%3};"
        : "+f"(c[0]), "+f"(c[1]), "+f"(c[2]), "+f"(c[3])
        : "r"(a[0]), "r"(a[1]), "r"(a[2]), "r"(a[3]), "r"(b[0]), "r"(b[1]));
}

// kpair (0..15) -> smem column: within each k16 group of 8 kpairs, place
// pair (t, t+4) adjacently so a fragment load is one LDS.64.
__device__ __forceinline__ int colmap(int kp) {
    return ((kp >> 3) << 3) | (((kp & 3) << 1) | ((kp >> 2) & 1));
}

// ---------------- GEMM: C[M,N] = A[M,K] @ B[K,N], bf16x2-split (3 MMA terms)
// Block 128x128, BK=32, 256 threads = 8 warps, warp tile 64x32.
#define GSTR 18   // smem row stride in uint32

template <bool RELU_BIAS>
__global__ void __launch_bounds__(256)
gemm_bf16x2(const float* __restrict__ A, const float* __restrict__ B,
            const float* __restrict__ bias, float* __restrict__ C,
            int M, int N, int K)
{
    __shared__ uint32_t Ahi[128][GSTR], Alo[128][GSTR];
    __shared__ uint32_t Bhi[128][GSTR], Blo[128][GSTR];

    const int tid  = threadIdx.x;
    const int wid  = tid >> 5;
    const int lane = tid & 31;
    const int g    = lane >> 2;
    const int t    = lane & 3;
    const int brow = blockIdx.y * 128;
    const int bcol = blockIdx.x * 128;
    const int wm   = (wid >> 2) * 64;   // 0 or 64
    const int wn   = (wid & 3) * 32;    // 0,32,64,96

    float acc[4][4][4];
    #pragma unroll
    for (int mt = 0; mt < 4; mt++)
        #pragma unroll
        for (int nt = 0; nt < 4; nt++)
            #pragma unroll
            for (int i = 0; i < 4; i++) acc[mt][nt][i] = 0.0f;

    for (int k0 = 0; k0 < K; k0 += 32) {
        // --- A tile 128x32: 1024 float4, 4 per thread; split+pack into smem
        #pragma unroll
        for (int q = 0; q < 4; q++) {
            int p   = tid + q * 256;
            int m   = p >> 3;
            int kq4 = p & 7;                 // float4 index along K
            float4 v = make_float4(0.f, 0.f, 0.f, 0.f);
            if (brow + m < M)
                v = *(const float4*)(A + (size_t)(brow + m) * K + k0 + kq4 * 4);
            uint32_t h0, l0, h1, l1;
            split_pack(v.x, v.y, h0, l0);    // kpair 2*kq4
            split_pack(v.z, v.w, h1, l1);    // kpair 2*kq4+1
            int c0 = colmap(2 * kq4), c1 = colmap(2 * kq4 + 1);
            Ahi[m][c0] = h0; Alo[m][c0] = l0;
            Ahi[m][c1] = h1; Alo[m][c1] = l1;
        }
        // --- B tile 32x128: pairs along k from two adjacent rows of B
        #pragma unroll
        for (int q = 0; q < 2; q++) {
            int p  = tid + q * 256;          // 0..511
            int kp = p >> 5;                 // kpair 0..15
            int n4 = p & 31;                 // float4 index along N
            const float* r0 = B + (size_t)(k0 + 2 * kp) * N + bcol + n4 * 4;
            float4 v0 = *(const float4*)r0;
            float4 v1 = *(const float4*)(r0 + N);
            int c = colmap(kp);
            uint32_t h, l;
            split_pack(v0.x, v1.x, h, l); Bhi[n4 * 4 + 0][c] = h; Blo[n4 * 4 + 0][c] = l;
            split_pack(v0.y, v1.y, h, l); Bhi[n4 * 4 + 1][c] = h; Blo[n4 * 4 + 1][c] = l;
            split_pack(v0.z, v1.z, h, l); Bhi[n4 * 4 + 2][c] = h; Blo[n4 * 4 + 2][c] = l;
            split_pack(v0.w, v1.w, h, l); Bhi[n4 * 4 + 3][c] = h; Blo[n4 * 4 + 3][c] = l;
        }
        __syncthreads();

        #pragma unroll
        for (int s = 0; s < 2; s++) {        // two k16 steps
            const int cb = s * 8 + 2 * t;
            uint32_t ah[4][4], al[4][4];
            #pragma unroll
            for (int mt = 0; mt < 4; mt++) {
                int r = wm + mt * 16;
                uint2 p0 = *(const uint2*)&Ahi[r + g    ][cb];
                uint2 p1 = *(const uint2*)&Ahi[r + g + 8][cb];
                ah[mt][0] = p0.x; ah[mt][2] = p0.y;
                ah[mt][1] = p1.x; ah[mt][3] = p1.y;
                uint2 q0 = *(const uint2*)&Alo[r + g    ][cb];
                uint2 q1 = *(const uint2*)&Alo[r + g + 8][cb];
                al[mt][0] = q0.x; al[mt][2] = q0.y;
                al[mt][1] = q1.x; al[mt][3] = q1.y;
            }
            #pragma unroll
            for (int nt = 0; nt < 4; nt++) {
                uint2 bh2 = *(const uint2*)&Bhi[wn + nt * 8 + g][cb];
                uint2 bl2 = *(const uint2*)&Blo[wn + nt * 8 + g][cb];
                uint32_t bh[2] = {bh2.x, bh2.y};
                uint32_t bl[2] = {bl2.x, bl2.y};
                #pragma unroll
                for (int mt = 0; mt < 4; mt++) {
                    mma16(acc[mt][nt], ah[mt], bh);
                    mma16(acc[mt][nt], ah[mt], bl);
                    mma16(acc[mt][nt], al[mt], bh);
                }
            }
        }
        __syncthreads();
    }

    // epilogue: optional bias+relu, float2 stores
    #pragma unroll
    for (int nt = 0; nt < 4; nt++) {
        int col = bcol + wn + nt * 8 + 2 * t;
        float b0 = 0.f, b1 = 0.f;
        if (RELU_BIAS) { b0 = bias[col]; b1 = bias[col + 1]; }
        #pragma unroll
        for (int mt = 0; mt < 4; mt++) {
            int r0 = brow + wm + mt * 16 + g;
            float2 v0 = make_float2(acc[mt][nt][0] + b0, acc[mt][nt][1] + b1);
            float2 v1 = make_float2(acc[mt][nt][2] + b0, acc[mt][nt][3] + b1);
            if (RELU_BIAS) {
                v0.x = fmaxf(v0.x, 0.f); v0.y = fmaxf(v0.y, 0.f);
                v1.x = fmaxf(v1.x, 0.f); v1.y = fmaxf(v1.y, 0.f);
            }
            if (r0 < M)     *(float2*)(C + (size_t)r0 * N + col) = v0;
            if (r0 + 8 < M) *(float2*)(C + (size_t)(r0 + 8) * N + col) = v1;
        }
    }
}

// ---------------- aggregation (128 cols): warp per node ----------------------
template <bool ADD_BIAS>
__global__ void __launch_bounds__(256)
agg128(const float* __restrict__ xw, const float* __restrict__ bias,
       float* __restrict__ out, int n)
{
    int node = (blockIdx.x * 256 + threadIdx.x) >> 5;
    int lane = threadIdx.x & 31;
    if (node >= n) return;

    float dsq = g_dinv[node];
    dsq *= dsq;
    float4 tv = *((const float4*)xw + (size_t)node * 32 + lane);
    float4 acc = make_float4(tv.x * dsq, tv.y * dsq, tv.z * dsq, tv.w * dsq);

    int r0 = g_rowptr[node];
    int c  = g_cnt[node];
    for (int j = r0; j < r0 + c; j++) {
        int   s = g_csr_src[j];
        float w = g_csr_w[j];
        float4 p = *((const float4*)xw + (size_t)s * 32 + lane);
        acc.x = fmaf(p.x, w, acc.x);
        acc.y = fmaf(p.y, w, acc.y);
        acc.z = fmaf(p.z, w, acc.z);
        acc.w = fmaf(p.w, w, acc.w);
    }

    if (ADD_BIAS) {
        float4 b = *((const float4*)bias + lane);
        acc.x += b.x; acc.y += b.y; acc.z += b.z; acc.w += b.w;
    }
    *((float4*)out + (size_t)node * 32 + lane) = acc;
}

// ---------------- launch -----------------------------------------------------
extern "C" void kernel_launch(void* const* d_in, const int* in_sizes, int n_in,
                              void* d_out, int out_size)
{
    const float* emb = (const float*)d_in[0];   // [N, D]
    const float* W1  = (const float*)d_in[1];   // [D, H]
    const float* b1  = (const float*)d_in[2];   // [H]
    const float* W2  = (const float*)d_in[3];   // [H, D]
    const float* b2  = (const float*)d_in[4];   // [D]
    const void*  eix = d_in[5];                 // [2, E] int64 or int32
    float* out = (float*)d_out;                 // [N, D]

    const int D = in_sizes[4];          // 128
    const int H = in_sizes[2];          // 256
    const int N = in_sizes[0] / D;      // 100000
    const int E = in_sizes[5] / 2;      // 1600000
    const int NB = (N + 1023) / 1024;   // scan blocks (98)

    float *p_aggemb, *p_x, *p_xw2;
    cudaGetSymbolAddress((void**)&p_aggemb, g_aggemb);
    cudaGetSymbolAddress((void**)&p_x,      g_x);
    cudaGetSymbolAddress((void**)&p_xw2,    g_xw2);

    // ---- graph prep (5 kernels) ----
    zero_detect_kernel<<<(N + 255) / 256, 256>>>((const unsigned int*)eix, N);
    convert_count_kernel<<<(E + 255) / 256, 256>>>(eix, E);
    scanblock_dinv_kernel<<<NB, 1024>>>(N);
    add_offsets_kernel<<<(N + 255) / 256, 256>>>(N, NB);
    csr_fill_kernel<<<(E + 255) / 256, 256>>>(E);

    // ---- layer 1: aggemb = agg(emb); x = relu(aggemb @ W1 + b1) ----
    agg128<false><<<(N + 7) / 8, 256>>>(emb, nullptr, p_aggemb, N);
    {
        dim3 grid(H / 128, (N + 127) / 128);
        gemm_bf16x2<true><<<grid, 256>>>(p_aggemb, W1, b1, p_x, N, H, D);
    }

    // ---- layer 2: xw2 = x @ W2; out = agg(xw2) + b2 ----
    {
        dim3 grid(D / 128, (N + 127) / 128);
        gemm_bf16x2<false><<<grid, 256>>>(p_x, W2, nullptr, p_xw2, N, D, H);
    }
    agg128<true><<<(N + 7) / 8, 256>>>(p_xw2, b2, out, N);
}

// round 4
// speedup vs baseline: 1.7075x; 1.2416x over previous
#include <cuda_runtime.h>
#include <cuda_bf16.h>
#include <cstdint>

// Problem constants (GCNEncoder_55052890800619)
#define NN 100000
#define DD 128
#define HH 256
#define EE 1600000

// ---------------- scratch (device globals; no allocations allowed) ----------
__device__ int   g_is64;
__device__ int   g_cnt[NN];
__device__ int   g_rowptr[NN];
__device__ int   g_cursor[NN];
__device__ float g_dinv[NN];
__device__ int   g_bsums[128];
__device__ int2  g_csr[EE];                  // {src, w bits} 12.8 MB
__device__ float g_aggemb[(size_t)NN * DD];  // 51.2 MB  agg(emb)
__device__ float g_x     [(size_t)NN * HH];  // 102.4 MB relu(agg(emb)@W1+b1)
__device__ float g_xw2   [(size_t)NN * DD];  // 51.2 MB  x@W2

// ---------------- prep kernels ----------------------------------------------
// 1) zero counts + dtype detect (warp-parallel sampling in block 0)
__global__ void zero_detect_kernel(const unsigned int* __restrict__ p, int n) {
    int i = blockIdx.x * blockDim.x + threadIdx.x;
    if (i < n) g_cnt[i] = 0;
    if (blockIdx.x == 0 && threadIdx.x < 32) {
        int any = 0;
        #pragma unroll
        for (int q = 0; q < 2; q++) {
            long long j = (long long)(threadIdx.x * 2 + q) * 24999 + 7;
            any |= (p[2 * j + 1] != 0u);
        }
        any = __any_sync(0xffffffffu, any);
        if (threadIdx.x == 0) g_is64 = any ? 0 : 1;
    }
}

__device__ __forceinline__ int2 load_edge(const void* eptr, int E, int e, int is64) {
    int2 r;
    if (is64) {
        const long long* q = (const long long*)eptr;
        r.x = (int)q[e];
        r.y = (int)q[(size_t)E + e];
    } else {
        const int* q = (const int*)eptr;
        r.x = q[e];
        r.y = q[(size_t)E + e];
    }
    return r;
}

// 2) degree count
__global__ void count_kernel(const void* __restrict__ eptr, int E) {
    int e = blockIdx.x * blockDim.x + threadIdx.x;
    if (e >= E) return;
    int2 sd = load_edge(eptr, E, e, g_is64);
    atomicAdd(&g_cnt[sd.y], 1);
}

// 3) per-1024-block exclusive scan of counts + dinv
__global__ void scanblock_dinv_kernel(int n) {
    __shared__ int sh[1024];
    int gid = blockIdx.x * 1024 + threadIdx.x;
    int v = (gid < n) ? g_cnt[gid] : 0;
    if (gid < n) g_dinv[gid] = rsqrtf((float)v + 1.0f);
    sh[threadIdx.x] = v;
    __syncthreads();
    for (int off = 1; off < 1024; off <<= 1) {
        int t = (threadIdx.x >= (unsigned)off) ? sh[threadIdx.x - off] : 0;
        __syncthreads();
        sh[threadIdx.x] += t;
        __syncthreads();
    }
    if (gid < n) g_rowptr[gid] = sh[threadIdx.x] - v;   // exclusive within block
    if (threadIdx.x == 1023) g_bsums[blockIdx.x] = sh[1023];
}

// 4) add block offsets (each block redundantly scans the <=128 block sums)
__global__ void add_offsets_kernel(int n, int nb) {
    __shared__ int sh[128];
    int tid = threadIdx.x;
    if (tid < 128) sh[tid] = (tid < nb) ? g_bsums[tid] : 0;
    __syncthreads();
    for (int off = 1; off < 128; off <<= 1) {
        int t = (tid >= (unsigned)off && tid < 128) ? sh[tid - off] : 0;
        __syncthreads();
        if (tid < 128) sh[tid] += t;
        __syncthreads();
    }
    int i = blockIdx.x * 256 + tid;
    if (i >= n) return;
    int j = i >> 10;
    int off = (j == 0) ? 0 : sh[j - 1];
    int r = g_rowptr[i] + off;
    g_rowptr[i] = r;
    g_cursor[i] = r;
}

// 5) scatter edges into packed CSR (one 8B store per edge)
__global__ void csr_fill_kernel(const void* __restrict__ eptr, int E) {
    int e = blockIdx.x * blockDim.x + threadIdx.x;
    if (e >= E) return;
    int2 sd = load_edge(eptr, E, e, g_is64);
    int pos = atomicAdd(&g_cursor[sd.y], 1);
    float w = g_dinv[sd.x] * g_dinv[sd.y];
    g_csr[pos] = make_int2(sd.x, __float_as_int(w));
}

// ---------------- bf16 split helpers ----------------------------------------
__device__ __forceinline__ void split_pack(float x0, float x1,
                                           uint32_t& hi, uint32_t& lo) {
    uint32_t h;
    asm("cvt.rn.bf16x2.f32 %0, %1, %2;" : "=r"(h) : "f"(x1), "f"(x0));
    float e0 = x0 - __uint_as_float(h << 16);
    float e1 = x1 - __uint_as_float(h & 0xffff0000u);
    asm("cvt.rn.bf16x2.f32 %0, %1, %2;" : "=r"(lo) : "f"(e1), "f"(e0));
    hi = h;
}

__device__ __forceinline__ void mma16(float* c, const uint32_t* a, const uint32_t* b) {
    asm volatile(
        "mma.sync.aligned.m16n8k16.row.col.f32.bf16.bf16.f32 "
        "{%0,%1,%2,%3}, {%4,%5,%6,%7}, {%8,%9}, {%0,%1,%2,%3};"
        : "+f"(c[0]), "+f"(c[1]), "+f"(c[2]), "+f"(c[3])
        : "r"(a[0]), "r"(a[1]), "r"(a[2]), "r"(a[3]), "r"(b[0]), "r"(b[1]));
}

// kpair (0..7) -> smem column: place pair (t, t+4) adjacently so a fragment
// load is one LDS.64.
__device__ __forceinline__ int colmap(int kp) {
    return ((kp & 3) << 1) | ((kp >> 2) & 1);
}

// ---------------- GEMM: C[M,N] = A[M,K] @ B[K,N], bf16x2-split (3 MMA terms)
// Block 128x128, BK=16, 256 threads = 8 warps, warp tile 64x32, 2 CTAs/SM.
#define GSTR 10   // smem row stride in uint32 (8 data + 2 pad)

template <bool RELU_BIAS>
__global__ void __launch_bounds__(256, 2)
gemm_bf16x2(const float* __restrict__ A, const float* __restrict__ B,
            const float* __restrict__ bias, float* __restrict__ C,
            int M, int N, int K)
{
    __shared__ uint32_t Ahi[128][GSTR], Alo[128][GSTR];
    __shared__ uint32_t Bhi[128][GSTR], Blo[128][GSTR];

    const int tid  = threadIdx.x;
    const int wid  = tid >> 5;
    const int lane = tid & 31;
    const int g    = lane >> 2;
    const int t    = lane & 3;
    const int brow = blockIdx.y * 128;
    const int bcol = blockIdx.x * 128;
    const int wm   = (wid >> 2) * 64;   // 0 or 64
    const int wn   = (wid & 3) * 32;    // 0,32,64,96

    float acc[4][4][4];
    #pragma unroll
    for (int mt = 0; mt < 4; mt++)
        #pragma unroll
        for (int nt = 0; nt < 4; nt++)
            #pragma unroll
            for (int i = 0; i < 4; i++) acc[mt][nt][i] = 0.0f;

    for (int k0 = 0; k0 < K; k0 += 16) {
        // --- A tile 128x16: 512 float4, 2 per thread; split+pack into smem
        #pragma unroll
        for (int q = 0; q < 2; q++) {
            int p   = tid + q * 256;
            int m   = p >> 2;              // 0..127
            int kq4 = p & 3;               // float4 index along K
            float4 v = make_float4(0.f, 0.f, 0.f, 0.f);
            if (brow + m < M)
                v = *(const float4*)(A + (size_t)(brow + m) * K + k0 + kq4 * 4);
            uint32_t h0, l0, h1, l1;
            split_pack(v.x, v.y, h0, l0);
            split_pack(v.z, v.w, h1, l1);
            int c0 = colmap(2 * kq4), c1 = colmap(2 * kq4 + 1);
            Ahi[m][c0] = h0; Alo[m][c0] = l0;
            Ahi[m][c1] = h1; Alo[m][c1] = l1;
        }
        // --- B tile 16x128: pairs along k from two adjacent rows of B
        {
            int kp = tid >> 5;             // kpair 0..7
            int n4 = tid & 31;             // float4 index along N
            const float* r0 = B + (size_t)(k0 + 2 * kp) * N + bcol + n4 * 4;
            float4 v0 = *(const float4*)r0;
            float4 v1 = *(const float4*)(r0 + N);
            int c = colmap(kp);
            uint32_t h, l;
            split_pack(v0.x, v1.x, h, l); Bhi[n4 * 4 + 0][c] = h; Blo[n4 * 4 + 0][c] = l;
            split_pack(v0.y, v1.y, h, l); Bhi[n4 * 4 + 1][c] = h; Blo[n4 * 4 + 1][c] = l;
            split_pack(v0.z, v1.z, h, l); Bhi[n4 * 4 + 2][c] = h; Blo[n4 * 4 + 2][c] = l;
            split_pack(v0.w, v1.w, h, l); Bhi[n4 * 4 + 3][c] = h; Blo[n4 * 4 + 3][c] = l;
        }
        __syncthreads();

        {
            const int cb = 2 * t;
            uint32_t ah[4][4], al[4][4];
            #pragma unroll
            for (int mt = 0; mt < 4; mt++) {
                int r = wm + mt * 16;
                uint2 p0 = *(const uint2*)&Ahi[r + g    ][cb];
                uint2 p1 = *(const uint2*)&Ahi[r + g + 8][cb];
                ah[mt][0] = p0.x; ah[mt][2] = p0.y;
                ah[mt][1] = p1.x; ah[mt][3] = p1.y;
                uint2 q0 = *(const uint2*)&Alo[r + g    ][cb];
                uint2 q1 = *(const uint2*)&Alo[r + g + 8][cb];
                al[mt][0] = q0.x; al[mt][2] = q0.y;
                al[mt][1] = q1.x; al[mt][3] = q1.y;
            }
            #pragma unroll
            for (int nt = 0; nt < 4; nt++) {
                uint2 bh2 = *(const uint2*)&Bhi[wn + nt * 8 + g][cb];
                uint2 bl2 = *(const uint2*)&Blo[wn + nt * 8 + g][cb];
                uint32_t bh[2] = {bh2.x, bh2.y};
                uint32_t bl[2] = {bl2.x, bl2.y};
                #pragma unroll
                for (int mt = 0; mt < 4; mt++) {
                    mma16(acc[mt][nt], ah[mt], bh);
                    mma16(acc[mt][nt], ah[mt], bl);
                    mma16(acc[mt][nt], al[mt], bh);
                }
            }
        }
        __syncthreads();
    }

    // epilogue: optional bias+relu, float2 stores
    #pragma unroll
    for (int nt = 0; nt < 4; nt++) {
        int col = bcol + wn + nt * 8 + 2 * t;
        float b0 = 0.f, b1 = 0.f;
        if (RELU_BIAS) { b0 = bias[col]; b1 = bias[col + 1]; }
        #pragma unroll
        for (int mt = 0; mt < 4; mt++) {
            int r0 = brow + wm + mt * 16 + g;
            float2 v0 = make_float2(acc[mt][nt][0] + b0, acc[mt][nt][1] + b1);
            float2 v1 = make_float2(acc[mt][nt][2] + b0, acc[mt][nt][3] + b1);
            if (RELU_BIAS) {
                v0.x = fmaxf(v0.x, 0.f); v0.y = fmaxf(v0.y, 0.f);
                v1.x = fmaxf(v1.x, 0.f); v1.y = fmaxf(v1.y, 0.f);
            }
            if (r0 < M)     *(float2*)(C + (size_t)r0 * N + col) = v0;
            if (r0 + 8 < M) *(float2*)(C + (size_t)(r0 + 8) * N + col) = v1;
        }
    }
}

// ---------------- aggregation (128 cols): warp per node, MLP=4 --------------
template <bool ADD_BIAS>
__global__ void __launch_bounds__(256)
agg128(const float* __restrict__ xw, const float* __restrict__ bias,
       float* __restrict__ out, int n)
{
    int node = (blockIdx.x * 256 + threadIdx.x) >> 5;
    int lane = threadIdx.x & 31;
    if (node >= n) return;

    float dsq = g_dinv[node];
    dsq *= dsq;
    const float4* base = (const float4*)xw;
    float4 tv = base[(size_t)node * 32 + lane];
    float4 acc = make_float4(tv.x * dsq, tv.y * dsq, tv.z * dsq, tv.w * dsq);

    int j   = g_rowptr[node];
    int end = j + g_cnt[node];

    // main loop: 4 independent gathers in flight
    for (; j + 4 <= end; j += 4) {
        int2 e0 = g_csr[j], e1 = g_csr[j + 1], e2 = g_csr[j + 2], e3 = g_csr[j + 3];
        float4 p0 = base[(size_t)e0.x * 32 + lane];
        float4 p1 = base[(size_t)e1.x * 32 + lane];
        float4 p2 = base[(size_t)e2.x * 32 + lane];
        float4 p3 = base[(size_t)e3.x * 32 + lane];
        float w0 = __int_as_float(e0.y), w1 = __int_as_float(e1.y);
        float w2 = __int_as_float(e2.y), w3 = __int_as_float(e3.y);
        acc.x = fmaf(p0.x, w0, acc.x); acc.y = fmaf(p0.y, w0, acc.y);
        acc.z = fmaf(p0.z, w0, acc.z); acc.w = fmaf(p0.w, w0, acc.w);
        acc.x = fmaf(p1.x, w1, acc.x); acc.y = fmaf(p1.y, w1, acc.y);
        acc.z = fmaf(p1.z, w1, acc.z); acc.w = fmaf(p1.w, w1, acc.w);
        acc.x = fmaf(p2.x, w2, acc.x); acc.y = fmaf(p2.y, w2, acc.y);
        acc.z = fmaf(p2.z, w2, acc.z); acc.w = fmaf(p2.w, w2, acc.w);
        acc.x = fmaf(p3.x, w3, acc.x); acc.y = fmaf(p3.y, w3, acc.y);
        acc.z = fmaf(p3.z, w3, acc.z); acc.w = fmaf(p3.w, w3, acc.w);
    }
    for (; j < end; j++) {
        int2 e = g_csr[j];
        float w = __int_as_float(e.y);
        float4 p = base[(size_t)e.x * 32 + lane];
        acc.x = fmaf(p.x, w, acc.x); acc.y = fmaf(p.y, w, acc.y);
        acc.z = fmaf(p.z, w, acc.z); acc.w = fmaf(p.w, w, acc.w);
    }

    if (ADD_BIAS) {
        float4 b = *((const float4*)bias + lane);
        acc.x += b.x; acc.y += b.y; acc.z += b.z; acc.w += b.w;
    }
    *((float4*)out + (size_t)node * 32 + lane) = acc;
}

// ---------------- launch -----------------------------------------------------
extern "C" void kernel_launch(void* const* d_in, const int* in_sizes, int n_in,
                              void* d_out, int out_size)
{
    const float* emb = (const float*)d_in[0];   // [N, D]
    const float* W1  = (const float*)d_in[1];   // [D, H]
    const float* b1  = (const float*)d_in[2];   // [H]
    const float* W2  = (const float*)d_in[3];   // [H, D]
    const float* b2  = (const float*)d_in[4];   // [D]
    const void*  eix = d_in[5];                 // [2, E] int64 or int32
    float* out = (float*)d_out;                 // [N, D]

    const int D = in_sizes[4];          // 128
    const int H = in_sizes[2];          // 256
    const int N = in_sizes[0] / D;      // 100000
    const int E = in_sizes[5] / 2;      // 1600000
    const int NB = (N + 1023) / 1024;   // scan blocks (98)

    float *p_aggemb, *p_x, *p_xw2;
    cudaGetSymbolAddress((void**)&p_aggemb, g_aggemb);
    cudaGetSymbolAddress((void**)&p_x,      g_x);
    cudaGetSymbolAddress((void**)&p_xw2,    g_xw2);

    // ---- graph prep (5 kernels) ----
    zero_detect_kernel<<<(N + 255) / 256, 256>>>((const unsigned int*)eix, N);
    count_kernel<<<(E + 255) / 256, 256>>>(eix, E);
    scanblock_dinv_kernel<<<NB, 1024>>>(N);
    add_offsets_kernel<<<(N + 255) / 256, 256>>>(N, NB);
    csr_fill_kernel<<<(E + 255) / 256, 256>>>(eix, E);

    // ---- layer 1: aggemb = agg(emb); x = relu(aggemb @ W1 + b1) ----
    agg128<false><<<(N + 7) / 8, 256>>>(emb, nullptr, p_aggemb, N);
    {
        dim3 grid(H / 128, (N + 127) / 128);
        gemm_bf16x2<true><<<grid, 256>>>(p_aggemb, W1, b1, p_x, N, H, D);
    }

    // ---- layer 2: xw2 = x @ W2; out = agg(xw2) + b2 ----
    {
        dim3 grid(D / 128, (N + 127) / 128);
        gemm_bf16x2<false><<<grid, 256>>>(p_x, W2, nullptr, p_xw2, N, D, H);
    }
    agg128<true><<<(N + 7) / 8, 256>>>(p_xw2, b2, out, N);
}

// round 5
// speedup vs baseline: 1.7140x; 1.0038x over previous
#include <cuda_runtime.h>
#include <cuda_bf16.h>
#include <cstdint>

// Problem constants (GCNEncoder_55052890800619)
#define NN 100000
#define DD 128
#define HH 256
#define EE 1600000

// ---------------- scratch (device globals; no allocations allowed) ----------
__device__ int   g_is64;
__device__ int   g_cnt[NN];
__device__ int   g_rowptr[NN];
__device__ int   g_cursor[NN];
__device__ float g_dinv[NN];
__device__ int   g_bsums[128];
__device__ int2  g_csr[EE];                  // {src, w bits} 12.8 MB
__device__ float g_aggemb[(size_t)NN * DD];  // 51.2 MB  agg(emb)
__device__ float g_x     [(size_t)NN * HH];  // 102.4 MB relu(agg(emb)@W1+b1)
__device__ float g_xw2   [(size_t)NN * DD];  // 51.2 MB  x@W2

// ---------------- prep kernels ----------------------------------------------
// 1) zero counts + dtype detect (warp-parallel sampling in block 0)
__global__ void zero_detect_kernel(const unsigned int* __restrict__ p, int n) {
    int i = blockIdx.x * blockDim.x + threadIdx.x;
    if (i < n) g_cnt[i] = 0;
    if (blockIdx.x == 0 && threadIdx.x < 32) {
        int any = 0;
        #pragma unroll
        for (int q = 0; q < 2; q++) {
            long long j = (long long)(threadIdx.x * 2 + q) * 24999 + 7;
            any |= (p[2 * j + 1] != 0u);
        }
        any = __any_sync(0xffffffffu, any);
        if (threadIdx.x == 0) g_is64 = any ? 0 : 1;
    }
}

__device__ __forceinline__ int2 load_edge(const void* eptr, int E, int e, int is64) {
    int2 r;
    if (is64) {
        const long long* q = (const long long*)eptr;
        r.x = (int)q[e];
        r.y = (int)q[(size_t)E + e];
    } else {
        const int* q = (const int*)eptr;
        r.x = q[e];
        r.y = q[(size_t)E + e];
    }
    return r;
}

// 2) degree count (reads only the dst half of the edge list)
__global__ void count_kernel(const void* __restrict__ eptr, int E) {
    int e = blockIdx.x * blockDim.x + threadIdx.x;
    if (e >= E) return;
    int d;
    if (g_is64) d = (int)(((const long long*)eptr)[(size_t)E + e]);
    else        d = ((const int*)eptr)[(size_t)E + e];
    atomicAdd(&g_cnt[d], 1);
}

// 3) per-1024-block exclusive scan of counts + dinv
__global__ void scanblock_dinv_kernel(int n) {
    __shared__ int sh[1024];
    int gid = blockIdx.x * 1024 + threadIdx.x;
    int v = (gid < n) ? g_cnt[gid] : 0;
    if (gid < n) g_dinv[gid] = rsqrtf((float)v + 1.0f);
    sh[threadIdx.x] = v;
    __syncthreads();
    for (int off = 1; off < 1024; off <<= 1) {
        int t = (threadIdx.x >= (unsigned)off) ? sh[threadIdx.x - off] : 0;
        __syncthreads();
        sh[threadIdx.x] += t;
        __syncthreads();
    }
    if (gid < n) g_rowptr[gid] = sh[threadIdx.x] - v;   // exclusive within block
    if (threadIdx.x == 1023) g_bsums[blockIdx.x] = sh[1023];
}

// 4) add block offsets (each block redundantly scans the <=128 block sums)
__global__ void add_offsets_kernel(int n, int nb) {
    __shared__ int sh[128];
    int tid = threadIdx.x;
    if (tid < 128) sh[tid] = (tid < nb) ? g_bsums[tid] : 0;
    __syncthreads();
    for (int off = 1; off < 128; off <<= 1) {
        int t = (tid >= (unsigned)off && tid < 128) ? sh[tid - off] : 0;
        __syncthreads();
        if (tid < 128) sh[tid] += t;
        __syncthreads();
    }
    int i = blockIdx.x * 256 + tid;
    if (i >= n) return;
    int j = i >> 10;
    int off = (j == 0) ? 0 : sh[j - 1];
    int r = g_rowptr[i] + off;
    g_rowptr[i] = r;
    g_cursor[i] = r;
}

// 5) scatter edges into packed CSR (one 8B store per edge)
__global__ void csr_fill_kernel(const void* __restrict__ eptr, int E) {
    int e = blockIdx.x * blockDim.x + threadIdx.x;
    if (e >= E) return;
    int2 sd = load_edge(eptr, E, e, g_is64);
    int pos = atomicAdd(&g_cursor[sd.y], 1);
    float w = g_dinv[sd.x] * g_dinv[sd.y];
    g_csr[pos] = make_int2(sd.x, __float_as_int(w));
}

// ---------------- bf16 split helpers ----------------------------------------
__device__ __forceinline__ void split_pack(float x0, float x1,
                                           uint32_t& hi, uint32_t& lo) {
    uint32_t h;
    asm("cvt.rn.bf16x2.f32 %0, %1, %2;" : "=r"(h) : "f"(x1), "f"(x0));
    float e0 = x0 - __uint_as_float(h << 16);
    float e1 = x1 - __uint_as_float(h & 0xffff0000u);
    asm("cvt.rn.bf16x2.f32 %0, %1, %2;" : "=r"(lo) : "f"(e1), "f"(e0));
    hi = h;
}

__device__ __forceinline__ void mma16(float* c, const uint32_t* a, const uint32_t* b) {
    asm volatile(
        "mma.sync.aligned.m16n8k16.row.col.f32.bf16.bf16.f32 "
        "{%0,%1,%2,%3}, {%4,%5,%6,%7}, {%8,%9}, {%0,%1,%2,%3};"
        : "+f"(c[0]), "+f"(c[1]), "+f"(c[2]), "+f"(c[3])
        : "r"(a[0]), "r"(a[1]), "r"(a[2]), "r"(a[3]), "r"(b[0]), "r"(b[1]));
}

// kpair (0..7) -> smem column: place pair (t, t+4) adjacently so a fragment
// load is one LDS.64.
__device__ __forceinline__ int colmap(int kp) {
    return ((kp & 3) << 1) | ((kp >> 2) & 1);
}

// ---------------- GEMM: C[M,N] = A[M,K] @ B[K,N], bf16x2-split (3 MMA terms)
// Block 128x128, BK=16, 256 threads = 8 warps, warp tile 64x32, 2 CTAs/SM.
#define GSTR 10   // smem row stride in uint32 (8 data + 2 pad)

template <bool RELU_BIAS>
__global__ void __launch_bounds__(256, 2)
gemm_bf16x2(const float* __restrict__ A, const float* __restrict__ B,
            const float* __restrict__ bias, float* __restrict__ C,
            int M, int N, int K)
{
    __shared__ uint32_t Ahi[128][GSTR], Alo[128][GSTR];
    __shared__ uint32_t Bhi[128][GSTR], Blo[128][GSTR];

    const int tid  = threadIdx.x;
    const int wid  = tid >> 5;
    const int lane = tid & 31;
    const int g    = lane >> 2;
    const int t    = lane & 3;
    const int brow = blockIdx.y * 128;
    const int bcol = blockIdx.x * 128;
    const int wm   = (wid >> 2) * 64;   // 0 or 64
    const int wn   = (wid & 3) * 32;    // 0,32,64,96

    float acc[4][4][4];
    #pragma unroll
    for (int mt = 0; mt < 4; mt++)
        #pragma unroll
        for (int nt = 0; nt < 4; nt++)
            #pragma unroll
            for (int i = 0; i < 4; i++) acc[mt][nt][i] = 0.0f;

    for (int k0 = 0; k0 < K; k0 += 16) {
        // --- A tile 128x16: 512 float4, 2 per thread; split+pack into smem
        #pragma unroll
        for (int q = 0; q < 2; q++) {
            int p   = tid + q * 256;
            int m   = p >> 2;              // 0..127
            int kq4 = p & 3;               // float4 index along K
            float4 v = make_float4(0.f, 0.f, 0.f, 0.f);
            if (brow + m < M)
                v = *(const float4*)(A + (size_t)(brow + m) * K + k0 + kq4 * 4);
            uint32_t h0, l0, h1, l1;
            split_pack(v.x, v.y, h0, l0);
            split_pack(v.z, v.w, h1, l1);
            int c0 = colmap(2 * kq4), c1 = colmap(2 * kq4 + 1);
            Ahi[m][c0] = h0; Alo[m][c0] = l0;
            Ahi[m][c1] = h1; Alo[m][c1] = l1;
        }
        // --- B tile 16x128: pairs along k from two adjacent rows of B
        {
            int kp = tid >> 5;             // kpair 0..7
            int n4 = tid & 31;             // float4 index along N
            const float* r0 = B + (size_t)(k0 + 2 * kp) * N + bcol + n4 * 4;
            float4 v0 = *(const float4*)r0;
            float4 v1 = *(const float4*)(r0 + N);
            int c = colmap(kp);
            uint32_t h, l;
            split_pack(v0.x, v1.x, h, l); Bhi[n4 * 4 + 0][c] = h; Blo[n4 * 4 + 0][c] = l;
            split_pack(v0.y, v1.y, h, l); Bhi[n4 * 4 + 1][c] = h; Blo[n4 * 4 + 1][c] = l;
            split_pack(v0.z, v1.z, h, l); Bhi[n4 * 4 + 2][c] = h; Blo[n4 * 4 + 2][c] = l;
            split_pack(v0.w, v1.w, h, l); Bhi[n4 * 4 + 3][c] = h; Blo[n4 * 4 + 3][c] = l;
        }
        __syncthreads();

        {
            const int cb = 2 * t;
            uint32_t ah[4][4], al[4][4];
            #pragma unroll
            for (int mt = 0; mt < 4; mt++) {
                int r = wm + mt * 16;
                uint2 p0 = *(const uint2*)&Ahi[r + g    ][cb];
                uint2 p1 = *(const uint2*)&Ahi[r + g + 8][cb];
                ah[mt][0] = p0.x; ah[mt][2] = p0.y;
                ah[mt][1] = p1.x; ah[mt][3] = p1.y;
                uint2 q0 = *(const uint2*)&Alo[r + g    ][cb];
                uint2 q1 = *(const uint2*)&Alo[r + g + 8][cb];
                al[mt][0] = q0.x; al[mt][2] = q0.y;
                al[mt][1] = q1.x; al[mt][3] = q1.y;
            }
            #pragma unroll
            for (int nt = 0; nt < 4; nt++) {
                uint2 bh2 = *(const uint2*)&Bhi[wn + nt * 8 + g][cb];
                uint2 bl2 = *(const uint2*)&Blo[wn + nt * 8 + g][cb];
                uint32_t bh[2] = {bh2.x, bh2.y};
                uint32_t bl[2] = {bl2.x, bl2.y};
                #pragma unroll
                for (int mt = 0; mt < 4; mt++) {
                    mma16(acc[mt][nt], ah[mt], bh);
                    mma16(acc[mt][nt], ah[mt], bl);
                    mma16(acc[mt][nt], al[mt], bh);
                }
            }
        }
        __syncthreads();
    }

    // epilogue: optional bias+relu, float2 stores
    #pragma unroll
    for (int nt = 0; nt < 4; nt++) {
        int col = bcol + wn + nt * 8 + 2 * t;
        float b0 = 0.f, b1 = 0.f;
        if (RELU_BIAS) { b0 = bias[col]; b1 = bias[col + 1]; }
        #pragma unroll
        for (int mt = 0; mt < 4; mt++) {
            int r0 = brow + wm + mt * 16 + g;
            float2 v0 = make_float2(acc[mt][nt][0] + b0, acc[mt][nt][1] + b1);
            float2 v1 = make_float2(acc[mt][nt][2] + b0, acc[mt][nt][3] + b1);
            if (RELU_BIAS) {
                v0.x = fmaxf(v0.x, 0.f); v0.y = fmaxf(v0.y, 0.f);
                v1.x = fmaxf(v1.x, 0.f); v1.y = fmaxf(v1.y, 0.f);
            }
            if (r0 < M)     *(float2*)(C + (size_t)r0 * N + col) = v0;
            if (r0 + 8 < M) *(float2*)(C + (size_t)(r0 + 8) * N + col) = v1;
        }
    }
}

// ---------------- aggregation (128 cols): warp per node, MLP=8 --------------
template <bool ADD_BIAS>
__global__ void __launch_bounds__(256)
agg128(const float* __restrict__ xw, const float* __restrict__ bias,
       float* __restrict__ out, int n)
{
    int node = (blockIdx.x * 256 + threadIdx.x) >> 5;
    int lane = threadIdx.x & 31;
    if (node >= n) return;

    float dsq = g_dinv[node];
    dsq *= dsq;
    const float4* base = (const float4*)xw;
    float4 tv = base[(size_t)node * 32 + lane];
    float4 acc = make_float4(tv.x * dsq, tv.y * dsq, tv.z * dsq, tv.w * dsq);

    int j   = g_rowptr[node];
    int end = j + g_cnt[node];

    // main loop: 8 independent gathers in flight
    for (; j + 8 <= end; j += 8) {
        int2 e[8];
        #pragma unroll
        for (int q = 0; q < 8; q++) e[q] = g_csr[j + q];
        float4 p[8];
        #pragma unroll
        for (int q = 0; q < 8; q++) p[q] = base[(size_t)e[q].x * 32 + lane];
        #pragma unroll
        for (int q = 0; q < 8; q++) {
            float w = __int_as_float(e[q].y);
            acc.x = fmaf(p[q].x, w, acc.x);
            acc.y = fmaf(p[q].y, w, acc.y);
            acc.z = fmaf(p[q].z, w, acc.z);
            acc.w = fmaf(p[q].w, w, acc.w);
        }
    }
    // remainder: 4-wide then scalar
    if (j + 4 <= end) {
        int2 e[4];
        #pragma unroll
        for (int q = 0; q < 4; q++) e[q] = g_csr[j + q];
        float4 p[4];
        #pragma unroll
        for (int q = 0; q < 4; q++) p[q] = base[(size_t)e[q].x * 32 + lane];
        #pragma unroll
        for (int q = 0; q < 4; q++) {
            float w = __int_as_float(e[q].y);
            acc.x = fmaf(p[q].x, w, acc.x);
            acc.y = fmaf(p[q].y, w, acc.y);
            acc.z = fmaf(p[q].z, w, acc.z);
            acc.w = fmaf(p[q].w, w, acc.w);
        }
        j += 4;
    }
    for (; j < end; j++) {
        int2 e = g_csr[j];
        float w = __int_as_float(e.y);
        float4 p = base[(size_t)e.x * 32 + lane];
        acc.x = fmaf(p.x, w, acc.x); acc.y = fmaf(p.y, w, acc.y);
        acc.z = fmaf(p.z, w, acc.z); acc.w = fmaf(p.w, w, acc.w);
    }

    if (ADD_BIAS) {
        float4 b = *((const float4*)bias + lane);
        acc.x += b.x; acc.y += b.y; acc.z += b.z; acc.w += b.w;
    }
    *((float4*)out + (size_t)node * 32 + lane) = acc;
}

// ---------------- launch -----------------------------------------------------
extern "C" void kernel_launch(void* const* d_in, const int* in_sizes, int n_in,
                              void* d_out, int out_size)
{
    const float* emb = (const float*)d_in[0];   // [N, D]
    const float* W1  = (const float*)d_in[1];   // [D, H]
    const float* b1  = (const float*)d_in[2];   // [H]
    const float* W2  = (const float*)d_in[3];   // [H, D]
    const float* b2  = (const float*)d_in[4];   // [D]
    const void*  eix = d_in[5];                 // [2, E] int64 or int32
    float* out = (float*)d_out;                 // [N, D]

    const int D = in_sizes[4];          // 128
    const int H = in_sizes[2];          // 256
    const int N = in_sizes[0] / D;      // 100000
    const int E = in_sizes[5] / 2;      // 1600000
    const int NB = (N + 1023) / 1024;   // scan blocks (98)

    float *p_aggemb, *p_x, *p_xw2;
    cudaGetSymbolAddress((void**)&p_aggemb, g_aggemb);
    cudaGetSymbolAddress((void**)&p_x,      g_x);
    cudaGetSymbolAddress((void**)&p_xw2,    g_xw2);

    // ---- graph prep (5 kernels) ----
    zero_detect_kernel<<<(N + 255) / 256, 256>>>((const unsigned int*)eix, N);
    count_kernel<<<(E + 255) / 256, 256>>>(eix, E);
    scanblock_dinv_kernel<<<NB, 1024>>>(N);
    add_offsets_kernel<<<(N + 255) / 256, 256>>>(N, NB);
    csr_fill_kernel<<<(E + 255) / 256, 256>>>(eix, E);

    // ---- layer 1: aggemb = agg(emb); x = relu(aggemb @ W1 + b1) ----
    agg128<false><<<(N + 7) / 8, 256>>>(emb, nullptr, p_aggemb, N);
    {
        dim3 grid(H / 128, (N + 127) / 128);
        gemm_bf16x2<true><<<grid, 256>>>(p_aggemb, W1, b1, p_x, N, H, D);
    }

    // ---- layer 2: xw2 = x @ W2; out = agg(xw2) + b2 ----
    {
        dim3 grid(D / 128, (N + 127) / 128);
        gemm_bf16x2<false><<<grid, 256>>>(p_x, W2, nullptr, p_xw2, N, D, H);
    }
    agg128<true><<<(N + 7) / 8, 256>>>(p_xw2, b2, out, N);
}